// round 3
// baseline (speedup 1.0000x reference)
#include <cuda_runtime.h>
#include <math.h>

// Problem dims (fixed by the reference)
#define BATCH   1024
#define IN_DIM  768
#define HID     512
#define OUT_DIM 256

// Scratch (allocation-free rule: __device__ globals)
__device__ float g_A[BATCH * HID];   // (combin @ W2^T + b2) * (scale*log2e)
__device__ float g_T[BATCH * HID];   // s_emb @ W1^T + b1
__device__ float g_M[BATCH * HID];   // relu(attn @ s_emb)

__device__ __forceinline__ float ex2f_(float x) {
    float y; asm("ex2.approx.f32 %0, %1;" : "=f"(y) : "f"(x)); return y;
}
__device__ __forceinline__ float rcpf_(float x) {
    float y; asm("rcp.approx.f32 %0, %1;" : "=f"(y) : "f"(x)); return y;
}

// Y[M,N] = (X[M,K] @ W[N,K]^T + bias[N]) * outscale
// 64x64 tile, BK=16, 256 threads, 4x4 micro-tile per thread. All dims are
// multiples of the tile sizes for this problem.
__global__ __launch_bounds__(256) void gemm_tn64(
    const float* __restrict__ X, const float* __restrict__ W,
    const float* __restrict__ bias, float* __restrict__ Y,
    int M, int N, int K, float outscale)
{
    __shared__ float Xs[16][68];   // [k][m], +4 pad keeps 16B alignment (68*4=272=16*17)
    __shared__ float Ws[16][68];   // [k][n]

    const int tid = threadIdx.x;
    const int tx  = tid & 15;        // n-direction
    const int ty  = tid >> 4;        // m-direction
    const int bm  = blockIdx.y * 64;
    const int bn  = blockIdx.x * 64;

    // Loader mapping: 256 threads fetch 64 rows x 16 cols as one float4 each.
    const int lr = tid >> 2;         // row 0..63
    const int lc = (tid & 3) << 2;   // col 0,4,8,12
    const float* Xp = X + (size_t)(bm + lr) * K + lc;
    const float* Wp = W + (size_t)(bn + lr) * K + lc;

    float acc[4][4];
#pragma unroll
    for (int i = 0; i < 4; i++)
#pragma unroll
        for (int j = 0; j < 4; j++) acc[i][j] = 0.f;

    for (int k0 = 0; k0 < K; k0 += 16) {
        float4 xv = *(const float4*)(Xp + k0);
        float4 wv = *(const float4*)(Wp + k0);
        __syncthreads();               // previous tile fully consumed
        Xs[lc + 0][lr] = xv.x; Xs[lc + 1][lr] = xv.y;
        Xs[lc + 2][lr] = xv.z; Xs[lc + 3][lr] = xv.w;
        Ws[lc + 0][lr] = wv.x; Ws[lc + 1][lr] = wv.y;
        Ws[lc + 2][lr] = wv.z; Ws[lc + 3][lr] = wv.w;
        __syncthreads();

#pragma unroll
        for (int kk = 0; kk < 16; kk++) {
            float4 xr = *(const float4*)&Xs[kk][ty << 2];
            float4 wr = *(const float4*)&Ws[kk][tx << 2];
            float xa[4] = {xr.x, xr.y, xr.z, xr.w};
            float wa[4] = {wr.x, wr.y, wr.z, wr.w};
#pragma unroll
            for (int i = 0; i < 4; i++)
#pragma unroll
                for (int j = 0; j < 4; j++)
                    acc[i][j] = fmaf(xa[i], wa[j], acc[i][j]);
        }
    }

    float4 bv = *(const float4*)(bias + bn + (tx << 2));
#pragma unroll
    for (int i = 0; i < 4; i++) {
        float4 o;
        o.x = (acc[i][0] + bv.x) * outscale;
        o.y = (acc[i][1] + bv.y) * outscale;
        o.z = (acc[i][2] + bv.z) * outscale;
        o.w = (acc[i][3] + bv.w) * outscale;
        *(float4*)(Y + (size_t)(bm + (ty << 2) + i) * N + bn + (tx << 2)) = o;
    }
}

// Per batch b: out[i] = relu( sum_j 2^(A_i * t_j) * s_j / sum_j 2^(A_i * t_j) )
// One CTA per batch row, 512 threads = one i per thread, t/s pairs staged in smem
// (broadcast LDS.64 per j). MUFU.EX2-bound by design.
__global__ __launch_bounds__(512) void attn512(
    const float* __restrict__ A, const float* __restrict__ T,
    const float* __restrict__ S, float* __restrict__ Mo)
{
    __shared__ float2 ts[HID];
    const int b = blockIdx.x;
    const int t = threadIdx.x;
    const float* Tr = T + (size_t)b * HID;
    const float* Sr = S + (size_t)b * HID;
    ts[t] = make_float2(Tr[t], Sr[t]);
    __syncthreads();

    const float a = A[(size_t)b * HID + t];
    float num = 0.f, den = 0.f;
#pragma unroll 8
    for (int j = 0; j < HID; j++) {
        float2 p = ts[j];
        float e = ex2f_(a * p.x);
        num = fmaf(e, p.y, num);
        den += e;
    }
    float v = num * rcpf_(den);
    Mo[(size_t)b * HID + t] = v > 0.f ? v : 0.f;
}

extern "C" void kernel_launch(void* const* d_in, const int* in_sizes, int n_in,
                              void* d_out, int out_size)
{
    const float* combin = (const float*)d_in[0];
    const float* s_emb  = (const float*)d_in[1];
    const float* W1     = (const float*)d_in[2];
    const float* b1     = (const float*)d_in[3];
    const float* W2     = (const float*)d_in[4];
    const float* b2     = (const float*)d_in[5];
    const float* W3     = (const float*)d_in[6];
    const float* b3     = (const float*)d_in[7];
    float* out = (float*)d_out;

    float *A, *T, *Mo;
    cudaGetSymbolAddress((void**)&A,  g_A);
    cudaGetSymbolAddress((void**)&T,  g_T);
    cudaGetSymbolAddress((void**)&Mo, g_M);

    // Fold softmax scale and log2(e) into the A epilogue: exp(s*c*t) = 2^(A*t)
    const float osc = 1.4426950408889634f / sqrtf((float)HID);

    gemm_tn64<<<dim3(HID / 64, BATCH / 64), 256>>>(combin, W2, b2, A,
                                                   BATCH, HID, IN_DIM, osc);
    gemm_tn64<<<dim3(HID / 64, BATCH / 64), 256>>>(s_emb, W1, b1, T,
                                                   BATCH, HID, HID, 1.0f);
    attn512<<<BATCH, 512>>>(A, T, s_emb, Mo);
    gemm_tn64<<<dim3(OUT_DIM / 64, BATCH / 64), 256>>>(Mo, W3, b3, out,
                                                       BATCH, OUT_DIM, HID, 1.0f);
}

// round 5
// speedup vs baseline: 2.3891x; 2.3891x over previous
#include <cuda_runtime.h>
#include <cuda_bf16.h>
#include <math.h>

#define BATCH   1024
#define IN_DIM  768
#define HID     512
#define OUT_DIM 256

// Scratch (allocation-free rule: __device__ globals)
__device__ float g_A[BATCH * HID];   // c_emb * (1/sqrt(HID))  (natural-exp units)
__device__ float g_T[BATCH * HID];   // t_emb
__device__ float g_M[BATCH * HID];   // relu(attn @ s_emb)

__device__ __forceinline__ float ex2f_(float x) {
    float y; asm("ex2.approx.f32 %0, %1;" : "=f"(y) : "f"(x)); return y;
}
__device__ __forceinline__ float rcpf_(float x) {
    float y; asm("rcp.approx.f32 %0, %1;" : "=f"(y) : "f"(x)); return y;
}

// ---------------------------------------------------------------------------
// bf16 3-split tensor-core GEMM:  Y[M,N] = (X[M,K] @ W[N,K]^T + bias) * osc
// fp32 x split into (xh, xl); extended K (3x) interleave:
//   X' = [xh, xh, xl],  W' = [wh, wl, wh]  =>  dot = xh*wh + xh*wl + xl*wh
// CTA tile 64x64, BK=32 fp32 (96 ext), 8 warps (2x4), warp tile 32x16,
// mma.sync.m16n8k16 with ldmatrix from conflict-free smem (stride 104 elems).
// ---------------------------------------------------------------------------
#define BM 64
#define BN 64
#define BKF 32
#define NKS 6          // ext k16-steps per BKF: 3*32/16
#define STRIDE 104     // ushort elems per smem row (52 words, 52%32=20 -> conflict-free LDSM)

__device__ __forceinline__ void split2(float v, unsigned &h, unsigned &l) {
    __nv_bfloat16 hb = __float2bfloat16(v);
    float lo = v - __bfloat162float(hb);
    __nv_bfloat16 lb = __float2bfloat16(lo);
    h = (unsigned)__bfloat16_as_ushort(hb);
    l = (unsigned)__bfloat16_as_ushort(lb);
}

__device__ __forceinline__ void ldsm4(unsigned addr, unsigned &r0, unsigned &r1,
                                      unsigned &r2, unsigned &r3) {
    asm volatile("ldmatrix.sync.aligned.m8n8.x4.shared.b16 {%0,%1,%2,%3}, [%4];"
                 : "=r"(r0), "=r"(r1), "=r"(r2), "=r"(r3) : "r"(addr));
}

__device__ __forceinline__ void mma_bf16(float c[4], unsigned a0, unsigned a1,
                                         unsigned a2, unsigned a3,
                                         unsigned b0, unsigned b1) {
    asm volatile(
        "mma.sync.aligned.m16n8k16.row.col.f32.bf16.bf16.f32 "
        "{%0,%1,%2,%3}, {%4,%5,%6,%7}, {%8,%9}, {%0,%1,%2,%3};\n"
        : "+f"(c[0]), "+f"(c[1]), "+f"(c[2]), "+f"(c[3])
        : "r"(a0), "r"(a1), "r"(a2), "r"(a3), "r"(b0), "r"(b1));
}

__global__ __launch_bounds__(256) void gemm_bf3(
    const float* X0, const float* W0, const float* bias0, float* Y0, int K0, float osc0,
    const float* X1, const float* W1p, const float* bias1, float* Y1, int K1, float osc1,
    int N)
{
    __shared__ __align__(16) unsigned short As[BM * STRIDE];
    __shared__ __align__(16) unsigned short Bs[BN * STRIDE];

    const float* X; const float* W; const float* bias; float* Y; int K; float osc;
    if (blockIdx.z == 0) { X = X0; W = W0; bias = bias0; Y = Y0; K = K0; osc = osc0; }
    else                 { X = X1; W = W1p; bias = bias1; Y = Y1; K = K1; osc = osc1; }

    const int tid  = threadIdx.x;
    const int bm   = blockIdx.y * BM;
    const int bn   = blockIdx.x * BN;
    const int lrow = tid >> 2;            // 0..63
    const int lcol = (tid & 3) * 8;       // 0,8,16,24 (fp32 cols)

    const int wid  = tid >> 5;
    const int lane = tid & 31;
    const int wm0  = (wid >> 2) * 32;     // 0 / 32
    const int wn0  = (wid & 3) * 16;      // 0,16,32,48

    float acc[2][2][4];
#pragma unroll
    for (int i = 0; i < 2; i++)
#pragma unroll
        for (int j = 0; j < 2; j++)
#pragma unroll
            for (int r = 0; r < 4; r++) acc[i][j][r] = 0.f;

    const float* Xp = X + (size_t)(bm + lrow) * K + lcol;
    const float* Wp = W + (size_t)(bn + lrow) * K + lcol;

    // ldmatrix per-lane base addresses
    unsigned aAddr0 = (unsigned)__cvta_generic_to_shared(
        &As[(wm0 + (lane & 15)) * STRIDE + ((lane >> 4) << 3)]);
    unsigned aAddr1 = (unsigned)__cvta_generic_to_shared(
        &As[(wm0 + 16 + (lane & 15)) * STRIDE + ((lane >> 4) << 3)]);
    unsigned bAddr  = (unsigned)__cvta_generic_to_shared(
        &Bs[(wn0 + (lane & 7) + ((lane >> 4) << 3)) * STRIDE + (((lane >> 3) & 1) << 3)]);

    for (int k0 = 0; k0 < K; k0 += BKF) {
        float4 xv0 = *(const float4*)(Xp + k0);
        float4 xv1 = *(const float4*)(Xp + k0 + 4);
        float4 wv0 = *(const float4*)(Wp + k0);
        float4 wv1 = *(const float4*)(Wp + k0 + 4);
        __syncthreads();
        {
            float xa[8] = {xv0.x, xv0.y, xv0.z, xv0.w, xv1.x, xv1.y, xv1.z, xv1.w};
            float wa[8] = {wv0.x, wv0.y, wv0.z, wv0.w, wv1.x, wv1.y, wv1.z, wv1.w};
            unsigned* ap = (unsigned*)(As + lrow * STRIDE + lcol * 3);
            unsigned* bp = (unsigned*)(Bs + lrow * STRIDE + lcol * 3);
#pragma unroll
            for (int e = 0; e < 8; e += 2) {
                unsigned h0, l0, h1, l1;
                int wI = (e >> 1) * 3;
                split2(xa[e], h0, l0); split2(xa[e + 1], h1, l1);
                ap[wI + 0] = h0 | (h0 << 16);   // [xh0, xh0]
                ap[wI + 1] = l0 | (h1 << 16);   // [xl0, xh1]
                ap[wI + 2] = h1 | (l1 << 16);   // [xh1, xl1]
                split2(wa[e], h0, l0); split2(wa[e + 1], h1, l1);
                bp[wI + 0] = h0 | (l0 << 16);   // [wh0, wl0]
                bp[wI + 1] = h0 | (h1 << 16);   // [wh0, wh1]
                bp[wI + 2] = l1 | (h1 << 16);   // [wl1, wh1]
            }
        }
        __syncthreads();

#pragma unroll
        for (int ks = 0; ks < NKS; ks++) {
            unsigned a0[4], a1[4], b[4];
            ldsm4(aAddr0 + ks * 32, a0[0], a0[1], a0[2], a0[3]);
            ldsm4(aAddr1 + ks * 32, a1[0], a1[1], a1[2], a1[3]);
            ldsm4(bAddr  + ks * 32, b[0],  b[1],  b[2],  b[3]);
            mma_bf16(acc[0][0], a0[0], a0[1], a0[2], a0[3], b[0], b[1]);
            mma_bf16(acc[0][1], a0[0], a0[1], a0[2], a0[3], b[2], b[3]);
            mma_bf16(acc[1][0], a1[0], a1[1], a1[2], a1[3], b[0], b[1]);
            mma_bf16(acc[1][1], a1[0], a1[1], a1[2], a1[3], b[2], b[3]);
        }
    }

    const int g  = lane >> 2;
    const int cc = (lane & 3) * 2;
#pragma unroll
    for (int mt = 0; mt < 2; mt++)
#pragma unroll
        for (int nt = 0; nt < 2; nt++) {
            int col = bn + wn0 + nt * 8 + cc;
            float2 bv = *(const float2*)(bias + col);
            int row0 = bm + wm0 + mt * 16 + g;
            float2 o0, o1;
            o0.x = (acc[mt][nt][0] + bv.x) * osc;
            o0.y = (acc[mt][nt][1] + bv.y) * osc;
            o1.x = (acc[mt][nt][2] + bv.x) * osc;
            o1.y = (acc[mt][nt][3] + bv.y) * osc;
            *(float2*)(Y + (size_t)row0 * N + col)       = o0;
            *(float2*)(Y + (size_t)(row0 + 8) * N + col) = o1;
        }
}

// ---------------------------------------------------------------------------
// Chebyshev attention. Per batch b: out_i = relu(f(a_i)),
//   f(a) = sum_j s_j e^{a t_j} / sum_j e^{a t_j}
// Evaluate N(a), D(a) at 16 Chebyshev nodes over [a_min, a_max] (warp w = node
// w), DCT -> Chebyshev coeffs, Clenshaw eval per i. ~32x fewer ex2.
// ---------------------------------------------------------------------------
#define NNODE 16
__global__ __launch_bounds__(512) void attn_cheb(
    const float* __restrict__ A, const float* __restrict__ T,
    const float* __restrict__ S, float* __restrict__ Mo)
{
    __shared__ float tex[HID], ssh[HID];
    __shared__ float rmin[16], rmax[16];
    __shared__ float nodeN[NNODE], nodeD[NNODE];
    __shared__ float cN[NNODE], cD[NNODE];
    __shared__ float mh[2];

    const int b = blockIdx.x;
    const int tid = threadIdx.x;
    const int lane = tid & 31;
    const int w = tid >> 5;          // 16 warps

    tex[tid] = T[(size_t)b * HID + tid] * 1.44269504088896f;  // fold log2(e)
    ssh[tid] = S[(size_t)b * HID + tid];
    float a = A[(size_t)b * HID + tid];

    float mn = a, mx = a;
#pragma unroll
    for (int o = 16; o; o >>= 1) {
        mn = fminf(mn, __shfl_xor_sync(0xffffffffu, mn, o));
        mx = fmaxf(mx, __shfl_xor_sync(0xffffffffu, mx, o));
    }
    if (lane == 0) { rmin[w] = mn; rmax[w] = mx; }
    __syncthreads();
    if (tid == 0) {
        float mn2 = rmin[0], mx2 = rmax[0];
#pragma unroll
        for (int i = 1; i < 16; i++) { mn2 = fminf(mn2, rmin[i]); mx2 = fmaxf(mx2, rmax[i]); }
        mh[0] = 0.5f * (mn2 + mx2);
        mh[1] = 0.5f * (mx2 - mn2) + 1e-12f;
    }
    __syncthreads();
    const float m = mh[0], h = mh[1];

    // node evaluation: warp w handles Chebyshev node w
    const float xk = fmaf(h, cospif((w + 0.5f) * (1.0f / NNODE)), m);
    float aN = 0.f, aD = 0.f;
#pragma unroll 8
    for (int j = lane; j < HID; j += 32) {
        float e = ex2f_(xk * tex[j]);
        aD += e;
        aN = fmaf(e, ssh[j], aN);
    }
#pragma unroll
    for (int o = 16; o; o >>= 1) {
        aN += __shfl_xor_sync(0xffffffffu, aN, o);
        aD += __shfl_xor_sync(0xffffffffu, aD, o);
    }
    if (lane == 0) { nodeN[w] = aN; nodeD[w] = aD; }
    __syncthreads();

    // DCT: 32 threads -> 16 N-coeffs + 16 D-coeffs
    if (tid < 32) {
        const int n = tid & 15;
        const float* V = (tid < 16) ? nodeN : nodeD;
        float c = 0.f;
#pragma unroll
        for (int k = 0; k < NNODE; k++)
            c += V[k] * cospif((float)(n * (2 * k + 1)) * (1.0f / 32.0f));
        c *= (n == 0) ? (1.0f / NNODE) : (2.0f / NNODE);
        ((tid < 16) ? cN : cD)[n] = c;
    }
    __syncthreads();

    // Clenshaw evaluation at u_i
    const float u = (a - m) * rcpf_(h);
    const float u2 = u + u;
    float bN1 = 0.f, bN2 = 0.f, bD1 = 0.f, bD2 = 0.f;
#pragma unroll
    for (int n = NNODE - 1; n >= 1; --n) {
        float tN = fmaf(u2, bN1, cN[n] - bN2);
        float tD = fmaf(u2, bD1, cD[n] - bD2);
        bN2 = bN1; bN1 = tN;
        bD2 = bD1; bD1 = tD;
    }
    float fN = fmaf(u, bN1, cN[0] - bN2);
    float fD = fmaf(u, bD1, cD[0] - bD2);
    float v = fN * rcpf_(fD);
    Mo[(size_t)b * HID + tid] = v > 0.f ? v : 0.f;
}

extern "C" void kernel_launch(void* const* d_in, const int* in_sizes, int n_in,
                              void* d_out, int out_size)
{
    const float* combin = (const float*)d_in[0];
    const float* s_emb  = (const float*)d_in[1];
    const float* W1     = (const float*)d_in[2];
    const float* b1     = (const float*)d_in[3];
    const float* W2     = (const float*)d_in[4];
    const float* b2     = (const float*)d_in[5];
    const float* W3     = (const float*)d_in[6];
    const float* b3     = (const float*)d_in[7];
    float* out = (float*)d_out;

    float *A, *T, *Mo;
    cudaGetSymbolAddress((void**)&A,  g_A);
    cudaGetSymbolAddress((void**)&T,  g_T);
    cudaGetSymbolAddress((void**)&Mo, g_M);

    const float sigma = 0.044194173824159216f;  // 1/sqrt(512), natural-exp units

    // GEMM1 (c_emb*sigma -> A) and GEMM2 (t_emb -> T) merged: blockIdx.z picks
    gemm_bf3<<<dim3(HID / BN, BATCH / BM, 2), 256>>>(
        combin, W2, b2, A, IN_DIM, sigma,
        s_emb,  W1, b1, T, HID,    1.0f,
        HID);

    attn_cheb<<<BATCH, 512>>>(A, T, s_emb, Mo);

    gemm_bf3<<<dim3(OUT_DIM / BN, BATCH / BM, 1), 256>>>(
        Mo, W3, b3, out, HID, 1.0f,
        Mo, W3, b3, out, HID, 1.0f,
        OUT_DIM);
}